// round 17
// baseline (speedup 1.0000x reference)
#include <cuda_runtime.h>
#include <cuda_fp16.h>
#include <math.h>
#include <cstdint>

#define NMAX 50000
#define NPAD 50176   // 392*128
#define EMAX 400000
#define DD   256
#define HH   128
#define G3   384
#define SROW 80                  // smem bytes per 32-halfword row
// hsht: A resident (128x256 fp16), B 2-stage chunks
#define AROW   528
#define A_RES  (128 * AROW)      // 67584
#define HB_TILE (128 * SROW)     // 10240
#define HSMEM  (A_RES + 2 * HB_TILE)  // 88064
// gru_fused: A1,A2 resident (128x128), B1,B2 resident (96x128)
#define GROW   272
#define G_TILE (128 * GROW)      // 34816
#define GB96   (96 * GROW)       // 26112
#define FSMEM  (2 * G_TILE + 2 * GB96)  // 121856

// ------------------- scratch -------------------
__device__ __align__(16) float  g_AS [3][NMAX];
__device__ __align__(16) float  g_AT [3][NMAX];
__device__ __align__(16) __half g_XU16[NPAD*DD], g_XI16[NPAD*DD];
__device__ __align__(16) __half g_HS16[3][NPAD*HH];
__device__ __align__(16) __half g_HT16[3][NPAD*HH];
__device__ __align__(16) __half g_AG16[3][NPAD*HH];
__device__ __align__(16) __half g_HO16[3][NPAD*HH];
__device__ __align__(16) __half g_WT16[6][128*DD];
__device__ __align__(16) __half g_WG16[6][G3*HH];   // gate-block-permuted rows
// CSR
__device__ int g_CNT [3*NMAX];
__device__ int g_OFF [3*NMAX];
__device__ int g_CUR [3*NMAX];
__device__ int g_SRC [3*EMAX];
__device__ int g_BSUM[256];

// ------------------- PTX helpers -------------------
__device__ __forceinline__ uint32_t smem_u32(const void* p) {
    uint32_t a;
    asm("{ .reg .u64 t; cvta.to.shared.u64 t, %1; cvt.u32.u64 %0, t; }" : "=r"(a) : "l"(p));
    return a;
}
__device__ __forceinline__ void ldsm4(uint32_t* r, uint32_t addr) {
    asm volatile("ldmatrix.sync.aligned.m8n8.x4.shared.b16 {%0,%1,%2,%3}, [%4];"
                 : "=r"(r[0]), "=r"(r[1]), "=r"(r[2]), "=r"(r[3]) : "r"(addr));
}
__device__ __forceinline__ void ldsm1(uint32_t* r, uint32_t addr) {
    asm volatile("ldmatrix.sync.aligned.m8n8.x1.shared.b16 {%0}, [%1];"
                 : "=r"(r[0]) : "r"(addr));
}
__device__ __forceinline__ void mma_f16(float* d, const uint32_t* a, const uint32_t* b) {
    asm volatile(
        "mma.sync.aligned.m16n8k16.row.col.f32.f16.f16.f32 "
        "{%0,%1,%2,%3}, {%4,%5,%6,%7}, {%8,%9}, {%0,%1,%2,%3};"
        : "+f"(d[0]), "+f"(d[1]), "+f"(d[2]), "+f"(d[3])
        : "r"(a[0]), "r"(a[1]), "r"(a[2]), "r"(a[3]), "r"(b[0]), "r"(b[1]));
}
__device__ __forceinline__ void cpa16(uint32_t dst, const void* src) {
    asm volatile("cp.async.cg.shared.global [%0], [%1], 16;" :: "r"(dst), "l"(src));
}
__device__ __forceinline__ uint2 pack4h(float4 v) {
    __half h0 = __float2half_rn(v.x), h1 = __float2half_rn(v.y);
    __half h2 = __float2half_rn(v.z), h3 = __float2half_rn(v.w);
    uint2 p;
    p.x = ((uint32_t)__half_as_ushort(h1) << 16) | __half_as_ushort(h0);
    p.y = ((uint32_t)__half_as_ushort(h3) << 16) | __half_as_ushort(h2);
    return p;
}
__device__ __forceinline__ float4 unpack4h(uint2 p) {
    __half2 a = *reinterpret_cast<__half2*>(&p.x);
    __half2 b = *reinterpret_cast<__half2*>(&p.y);
    float2 fa = __half22float2(a);
    float2 fb = __half22float2(b);
    return make_float4(fa.x, fa.y, fb.x, fb.y);
}

// ------------- fused prep (WG rows gate-block permuted) -------------
#define WT_TOT (6 * 128 * 256)
#define WG_TOT (6 * G3 * HH)
__global__ void prep_all(
    const float* xu, const float* xi, int n4,
    const float* a0, const float* a1, const float* a2,
    const float* a3, const float* a4, const float* a5,
    const float* g0, const float* g1, const float* g2,
    const float* g3, const float* g4, const float* g5)
{
    int i = blockIdx.x * blockDim.x + threadIdx.x;
    if (i < 2 * n4) {
        const float* src = (i < n4) ? xu : xi;
        int j = (i < n4) ? i : i - n4;
        float4 v = reinterpret_cast<const float4*>(src)[j];
        uint2 p = pack4h(v);
        if (i < n4) reinterpret_cast<uint2*>(g_XU16)[j] = p;
        else        reinterpret_cast<uint2*>(g_XI16)[j] = p;
        return;
    }
    int t = i - 2 * n4;
    if (t < WT_TOT) {
        const float* ws[6] = {a0, a1, a2, a3, a4, a5};
        int z = t >> 15, j = t & 32767;
        int n = j >> 8, k = j & 255;
        g_WT16[z][j] = __float2half_rn(ws[z][k * 128 + n]);
    } else if (t < WT_TOT + WG_TOT) {
        const float* ws[6] = {g0, g1, g2, g3, g4, g5};
        int u = t - WT_TOT;
        int z = u / (G3 * HH), j = u % (G3 * HH);
        int n = j >> 7, k = j & 127;
        int gate = n >> 7, h = n & 127;
        int hb = h >> 5, hl = h & 31;
        int rp = hb * 96 + gate * 32 + hl;       // permuted row
        g_WG16[z][rp * HH + k] = __float2half_rn(ws[z][j]);
    }
}

// -------- hsht GEMM: A resident, 2 weight sets per CTA, fused alpha --------
__global__ void __launch_bounds__(256, 2) hsht_gemm(
    int M, const float* q0, const float* q1, const float* q2)
{
    extern __shared__ char smem[];
    const int g = blockIdx.z;
    const __half* A16 = (g == 0) ? g_XU16 : g_XI16;
    const int zs0 = (g == 0) ? 0 : (g == 1) ? 1 : 4;
    const int zs1 = (g == 0) ? 3 : (g == 1) ? 2 : 5;
    const float* qs3[3] = {q0, q1, q2};
    const int m0 = blockIdx.x * 128;

    const uint32_t sb = smem_u32(smem);
    const uint32_t sA  = sb;
    const uint32_t sB0 = sb + A_RES;
    const int tid  = threadIdx.x;
    const int wid  = tid >> 5;
    const int lane = tid & 31;
    const int warp_m = wid & 3;
    const int warp_n = wid >> 2;

#pragma unroll
    for (int it = 0; it < 16; it++) {
        int s = tid + it * 256;
        int row = s >> 5, q = s & 31;
        cpa16(sA + row * AROW + q * 16, A16 + (size_t)(m0 + row) * DD + q * 8);
    }
    asm volatile("cp.async.commit_group;" ::: "memory");

#define FILLB(c) do {                                                           \
        const int zc_ = ((c) >> 3) ? zs1 : zs0;                                 \
        const int kc_ = (c) & 7;                                                \
        const uint32_t s0 = sB0 + ((c) & 1) * HB_TILE;                          \
        const __half* B16_ = g_WT16[zc_];                                       \
        _Pragma("unroll")                                                       \
        for (int it = 0; it < 2; it++) {                                        \
            int s = tid + it * 256;                                             \
            int row = s >> 2, q = s & 3;                                        \
            cpa16(s0 + row * SROW + q * 16,                                     \
                  B16_ + (size_t)row * DD + kc_ * 32 + q * 8);                  \
        }                                                                       \
        asm volatile("cp.async.commit_group;" ::: "memory");                    \
    } while (0)

    FILLB(0);

    float acc[2][8][4];
#pragma unroll
    for (int i = 0; i < 2; i++)
#pragma unroll
        for (int j = 0; j < 8; j++)
#pragma unroll
            for (int t = 0; t < 4; t++) acc[i][j][t] = 0.f;

    for (int c = 0; c < 16; c++) {
        if (c < 15) {
            FILLB(c + 1);
            asm volatile("cp.async.wait_group 1;" ::: "memory");
        } else {
            asm volatile("cp.async.wait_group 0;" ::: "memory");
        }
        __syncthreads();

        const int kc = c & 7;
        const uint32_t sB = sB0 + (c & 1) * HB_TILE;

#pragma unroll
        for (int ks = 0; ks < 2; ks++) {
            const int kglob = kc * 32 + ks * 16;
            uint32_t af[2][4];
            {
                int rr = lane & 15;
                int c8 = lane >> 4;
                uint32_t off = (uint32_t)((warp_m * 32 + rr) * AROW + (kglob + c8 * 8) * 2);
                ldsm4(af[0], sA + off);
                ldsm4(af[1], sA + off + 16 * AROW);
            }
            uint32_t bf[8][2];
            {
                int sub = lane >> 3, wi = lane & 7;
                int n_off = (sub >> 1) * 8 + wi;
                int k_off = ks * 16 + (sub & 1) * 8;
                uint32_t base = (uint32_t)((warp_n * 64 + n_off) * SROW + k_off * 2);
#pragma unroll
                for (int jj = 0; jj < 4; jj++) {
                    uint32_t r4[4];
                    ldsm4(r4, sB + base + jj * 16 * SROW);
                    bf[2 * jj][0] = r4[0]; bf[2 * jj][1] = r4[1];
                    bf[2 * jj + 1][0] = r4[2]; bf[2 * jj + 1][1] = r4[3];
                }
            }
#pragma unroll
            for (int mi = 0; mi < 2; mi++)
#pragma unroll
                for (int j = 0; j < 8; j++)
                    mma_f16(acc[mi][j], af[mi], bf[j]);
        }
        __syncthreads();

        if (kc == 7) {
            const int zc = (c >> 3) ? zs1 : zs0;
            const int which = zc & 1, r = zc >> 1;
            __half* C16 = which ? g_HT16[r] : g_HS16[r];
            float* alpha = which ? g_AT[r] : g_AS[r];
            const float* q = qs3[r] + which * HH;
#pragma unroll
            for (int mi = 0; mi < 2; mi++) {
#pragma unroll
                for (int half = 0; half < 2; half++) {
                    int row = m0 + warp_m * 32 + mi * 16 + half * 8 + (lane >> 2);
                    float dot = 0.f;
#pragma unroll
                    for (int j = 0; j < 8; j++) {
                        int gc = warp_n * 64 + j * 8 + 2 * (lane & 3);
                        float v0 = acc[mi][j][2 * half + 0];
                        float v1 = acc[mi][j][2 * half + 1];
                        if (row < M) {
                            __half2 hv = __floats2half2_rn(v0, v1);
                            *reinterpret_cast<__half2*>(C16 + (size_t)row * HH + gc) = hv;
                            dot += v0 * q[gc] + v1 * q[gc + 1];
                        }
                    }
                    dot += __shfl_xor_sync(0xffffffffu, dot, 1);
                    dot += __shfl_xor_sync(0xffffffffu, dot, 2);
                    if ((lane & 3) == 0 && row < M)
                        atomicAdd(alpha + row, dot);
                }
            }
#pragma unroll
            for (int i = 0; i < 2; i++)
#pragma unroll
                for (int j = 0; j < 8; j++)
#pragma unroll
                    for (int t = 0; t < 4; t++) acc[i][j][t] = 0.f;
        }
    }
#undef FILLB
}

// ---------- fused GRU: both gate GEMMs + combine, all operands resident ----
// grid(392, 4, 3): m-block, h-block(32 h), relation. Warp = 16m x 96n (3 gates).
__global__ void __launch_bounds__(256, 1) gru_fused(
    int M,
    const float* b0, const float* b1, const float* b2,
    const float* b3, const float* b4, const float* b5)
{
    extern __shared__ char smem[];
    const int r = blockIdx.z, hb = blockIdx.y;
    const float* biases[6] = {b0, b1, b2, b3, b4, b5};
    const float* bih = biases[2 * r];
    const float* bhh = biases[2 * r + 1];
    const __half* A1g = g_HT16[r];
    const __half* A2g = g_AG16[r];
    const __half* W1 = g_WG16[2 * r];      // permuted Wih
    const __half* W2 = g_WG16[2 * r + 1];  // permuted Whh
    const int m0 = blockIdx.x * 128;

    const uint32_t sb = smem_u32(smem);
    const uint32_t sA1 = sb;
    const uint32_t sA2 = sb + G_TILE;
    const uint32_t sB1 = sb + 2 * G_TILE;
    const uint32_t sB2 = sB1 + GB96;
    const int tid  = threadIdx.x;
    const int wid  = tid >> 5;
    const int lane = tid & 31;

    // ---- fill everything (resident): A1,A2: 8 each; B1,B2: 6 each per thread
#pragma unroll
    for (int it = 0; it < 8; it++) {
        int s = tid + it * 256;
        int row = s >> 4, q = s & 15;
        cpa16(sA1 + row * GROW + q * 16, A1g + (size_t)(m0 + row) * HH + q * 8);
        cpa16(sA2 + row * GROW + q * 16, A2g + (size_t)(m0 + row) * HH + q * 8);
    }
#pragma unroll
    for (int it = 0; it < 6; it++) {
        int s = tid + it * 256;
        int row = s >> 4, q = s & 15;   // row 0..95
        size_t src = (size_t)(hb * 96 + row) * HH + q * 8;
        cpa16(sB1 + row * GROW + q * 16, W1 + src);
        cpa16(sB2 + row * GROW + q * 16, W2 + src);
    }
    asm volatile("cp.async.commit_group;" ::: "memory");
    asm volatile("cp.async.wait_group 0;" ::: "memory");
    __syncthreads();

    float agi[12][4], agh[12][4];
#pragma unroll
    for (int j = 0; j < 12; j++)
#pragma unroll
        for (int t = 0; t < 4; t++) { agi[j][t] = 0.f; agh[j][t] = 0.f; }

#pragma unroll
    for (int ks = 0; ks < 8; ks++) {
        const int kglob = ks * 16;
        uint32_t af1[4], af2[4];
        {
            int rr = lane & 15;
            int c8 = lane >> 4;
            uint32_t off = (uint32_t)((wid * 16 + rr) * GROW + (kglob + c8 * 8) * 2);
            ldsm4(af1, sA1 + off);
            ldsm4(af2, sA2 + off);
        }
        uint32_t bf1[12][2], bf2[12][2];
        {
            int sub = lane >> 3, wi = lane & 7;
            int n_off = (sub >> 1) * 8 + wi;
            int k_off = kglob + (sub & 1) * 8;
            uint32_t base = (uint32_t)(n_off * GROW + k_off * 2);
#pragma unroll
            for (int jj = 0; jj < 6; jj++) {
                uint32_t r4[4];
                ldsm4(r4, sB1 + base + jj * 16 * GROW);
                bf1[2 * jj][0] = r4[0]; bf1[2 * jj][1] = r4[1];
                bf1[2 * jj + 1][0] = r4[2]; bf1[2 * jj + 1][1] = r4[3];
                ldsm4(r4, sB2 + base + jj * 16 * GROW);
                bf2[2 * jj][0] = r4[0]; bf2[2 * jj][1] = r4[1];
                bf2[2 * jj + 1][0] = r4[2]; bf2[2 * jj + 1][1] = r4[3];
            }
        }
#pragma unroll
        for (int j = 0; j < 12; j++) {
            mma_f16(agi[j], af1, bf1[j]);
            mma_f16(agh[j], af2, bf2[j]);
        }
    }

    // ---- fused GRU combine + HOUT write ----
    __half* HO = g_HO16[r];
#pragma unroll
    for (int half = 0; half < 2; half++) {
        int rowl = wid * 16 + half * 8 + (lane >> 2);
        int row = m0 + rowl;
        if (row >= M) continue;
#pragma unroll
        for (int j0 = 0; j0 < 4; j0++) {
            int c = 2 * (lane & 3) + 8 * j0;     // hl base (pair c, c+1)
            int h = hb * 32 + c;
#pragma unroll
            for (int u = 0; u < 2; u++) {
                float gi_r = agi[j0][2 * half + u]     + bih[h + u];
                float gi_z = agi[j0 + 4][2 * half + u] + bih[HH + h + u];
                float gi_n = agi[j0 + 8][2 * half + u] + bih[2 * HH + h + u];
                float gh_r = agh[j0][2 * half + u]     + bhh[h + u];
                float gh_z = agh[j0 + 4][2 * half + u] + bhh[HH + h + u];
                float gh_n = agh[j0 + 8][2 * half + u] + bhh[2 * HH + h + u];
                float rg = 1.f / (1.f + expf(-(gi_r + gh_r)));
                float zg = 1.f / (1.f + expf(-(gi_z + gh_z)));
                float ng = tanhf(gi_n + rg * gh_n);
                float av = __half2float(*reinterpret_cast<const __half*>(
                    smem + G_TILE + rowl * GROW + (h + u) * 2));
                float ho = (1.f - zg) * ng + zg * av;
                HO[(size_t)row * HH + h + u] = __float2half_rn(ho);
            }
        }
    }
}

// ------------------- CSR build -------------------
__global__ void hist_k(const int* e0, const int* e1, const int* e2, int E, int N)
{
    int e = blockIdx.x * blockDim.x + threadIdx.x;
    if (e >= 3 * E) return;
    int r = e / E, le = e - r * E;
    const int* ei = (r == 0) ? e0 : (r == 1) ? e1 : e2;
    atomicAdd(&g_CNT[r * N + ei[E + le]], 1);
}
__global__ void scan1_k(int ntot)
{
    __shared__ int sh[1024];
    int tid = threadIdx.x;
    int gid = blockIdx.x * 1024 + tid;
    int v = 0;
    if (gid < ntot) {
        v = g_CNT[gid];
        g_CNT[gid] = 0;
    }
    sh[tid] = v;
    __syncthreads();
    for (int o = 1; o < 1024; o <<= 1) {
        int t = (tid >= o) ? sh[tid - o] : 0;
        __syncthreads();
        sh[tid] += t;
        __syncthreads();
    }
    if (gid < ntot) g_OFF[gid] = sh[tid] - v;
    if (tid == 1023) g_BSUM[blockIdx.x] = sh[1023];
}
__global__ void scan3_k(int ntot)
{
    __shared__ int base;
    if (threadIdx.x < 32) {
        int run = 0;
        for (int i = threadIdx.x; i < blockIdx.x; i += 32) run += g_BSUM[i];
#pragma unroll
        for (int o = 16; o; o >>= 1) run += __shfl_xor_sync(0xffffffffu, run, o);
        if (threadIdx.x == 0) base = run;
    }
    __syncthreads();
    int gid = blockIdx.x * 1024 + threadIdx.x;
    if (gid >= ntot) return;
    int o = g_OFF[gid] + base;
    g_OFF[gid] = o;
    g_CUR[gid] = o;
    (&g_AS[0][0])[gid] = 0.f;
    (&g_AT[0][0])[gid] = 0.f;
}
__global__ void scatter_idx_k(const int* e0, const int* e1, const int* e2, int E, int N)
{
    int e = blockIdx.x * blockDim.x + threadIdx.x;
    if (e >= 3 * E) return;
    int r = e / E, le = e - r * E;
    const int* ei = (r == 0) ? e0 : (r == 1) ? e1 : e2;
    int si = ei[le];
    int ti = ei[E + le];
    int pos = atomicAdd(&g_CUR[r * N + ti], 1);
    g_SRC[pos] = si;
}

// ---------- gather aggregation ----------
__global__ void gather_k(int N, int Etot)
{
    int gw   = (blockIdx.x * blockDim.x + threadIdx.x) >> 5;
    int lane = threadIdx.x & 31;
    if (gw >= 3 * N) return;
    int r = gw / N, ti = gw - r * N;
    int idx = r * N + ti;
    int s = g_OFF[idx];
    int e = (idx + 1 < 3 * N) ? g_OFF[idx + 1] : Etot;
    uint2* dst16 = reinterpret_cast<uint2*>(g_AG16[r] + (size_t)ti * HH + lane * 4);
    float4 acc = make_float4(0.f, 0.f, 0.f, 0.f);
    if (s < e) {
        float at = g_AT[r][ti];
        float den = 0.f;
        for (int base = s; base < e; base += 32) {
            int k = base + lane;
            int si = 0;
            float ex = 0.f;
            if (k < e) {
                si = g_SRC[k];
                float l = g_AS[r][si] + at;
                l = (l > 0.f) ? l : 0.2f * l;
                ex = expf(l);
                den += ex;
            }
            int cnt = min(32, e - base);
            for (int j = 0; j < cnt; j++) {
                float exj = __shfl_sync(0xffffffffu, ex, j);
                int   sij = __shfl_sync(0xffffffffu, si, j);
                uint2 p = *reinterpret_cast<const uint2*>(
                    g_HS16[r] + (size_t)sij * HH + lane * 4);
                float4 v = unpack4h(p);
                acc.x += exj * v.x;
                acc.y += exj * v.y;
                acc.z += exj * v.z;
                acc.w += exj * v.w;
            }
        }
#pragma unroll
        for (int o = 16; o; o >>= 1) den += __shfl_xor_sync(0xffffffffu, den, o);
        float inv = 1.f / (den + 1e-16f);
        acc.x *= inv; acc.y *= inv; acc.z *= inv; acc.w *= inv;
    }
    *dst16 = pack4h(acc);
}

// ------- final semantic attention (reads HOUT fp16) -------
__global__ void final_sem_k(float* __restrict__ out, const float* __restrict__ g, int n)
{
    int node = (blockIdx.x * blockDim.x + threadIdx.x) >> 5;
    int lane = threadIdx.x & 31;
    if (node >= n) return;
    size_t off = (size_t)node * HH + lane * 4;

    float4 h1 = unpack4h(*reinterpret_cast<const uint2*>(g_HO16[1] + off));
    float4 u;
    u.x = fmaxf(h1.x, 0.f); u.y = fmaxf(h1.y, 0.f);
    u.z = fmaxf(h1.z, 0.f); u.w = fmaxf(h1.w, 0.f);
    *reinterpret_cast<float4*>(out + off) = u;

    float4 v0 = unpack4h(*reinterpret_cast<const uint2*>(g_HO16[0] + off));
    float4 v1 = unpack4h(*reinterpret_cast<const uint2*>(g_HO16[2] + off));
    float4 gv = *reinterpret_cast<const float4*>(g + lane * 4);
    float d0 = v0.x * gv.x + v0.y * gv.y + v0.z * gv.z + v0.w * gv.w;
    float d1 = v1.x * gv.x + v1.y * gv.y + v1.z * gv.z + v1.w * gv.w;
#pragma unroll
    for (int o = 16; o; o >>= 1) {
        d0 += __shfl_xor_sync(0xffffffffu, d0, o);
        d1 += __shfl_xor_sync(0xffffffffu, d1, o);
    }
    float a0 = expf(d0), a1 = expf(d1);
    float inv = 1.f / (a0 + a1);
    float w0 = a0 * inv, w1 = a1 * inv;
    float4 o4;
    o4.x = fmaxf(w0 * v0.x + w1 * v1.x, 0.f);
    o4.y = fmaxf(w0 * v0.y + w1 * v1.y, 0.f);
    o4.z = fmaxf(w0 * v0.z + w1 * v1.z, 0.f);
    o4.w = fmaxf(w0 * v0.w + w1 * v1.w, 0.f);
    *reinterpret_cast<float4*>(out + (size_t)n * HH + off) = o4;
}

// ---------------------------------------------------------------
extern "C" void kernel_launch(void* const* d_in, const int* in_sizes, int n_in,
                              void* d_out, int out_size)
{
    const float* x_user = (const float*)d_in[0];
    const float* x_item = (const float*)d_in[1];
    const int*   ei_ui  = (const int*)d_in[2];
    const int*   ei_iu  = (const int*)d_in[3];
    const int*   ei_ii  = (const int*)d_in[4];

    int N = in_sizes[0] / DD;
    int E = in_sizes[2] / 2;
    if (N > NMAX) N = NMAX;
    if (E > EMAX) E = EMAX;

    float* out = (float*)d_out;

    cudaFuncSetAttribute(hsht_gemm, cudaFuncAttributeMaxDynamicSharedMemorySize, HSMEM);
    cudaFuncSetAttribute(gru_fused, cudaFuncAttributeMaxDynamicSharedMemorySize, FSMEM);

    int x4 = (N * DD) / 4;
    int prepTot = 2 * x4 + WT_TOT + WG_TOT;
    prep_all<<<(prepTot + 255) / 256, 256>>>(
        x_user, x_item, x4,
        (const float*)d_in[5],  (const float*)d_in[6],
        (const float*)d_in[12], (const float*)d_in[13],
        (const float*)d_in[19], (const float*)d_in[20],
        (const float*)d_in[8],  (const float*)d_in[9],
        (const float*)d_in[15], (const float*)d_in[16],
        (const float*)d_in[22], (const float*)d_in[23]);

    int ntot = 3 * N;
    hist_k<<<(3 * E + 255) / 256, 256>>>(ei_ui, ei_iu, ei_ii, E, N);
    int nb = (ntot + 1023) / 1024;
    scan1_k<<<nb, 1024>>>(ntot);
    scan3_k<<<nb, 1024>>>(ntot);
    scatter_idx_k<<<(3 * E + 255) / 256, 256>>>(ei_ui, ei_iu, ei_ii, E, N);

    const int mb = NPAD / 128;   // 392

    hsht_gemm<<<dim3(mb, 1, 3), 256, HSMEM>>>(
        N, (const float*)d_in[7], (const float*)d_in[14], (const float*)d_in[21]);

    gather_k<<<(int)(((long long)3 * N * 32 + 255) / 256), 256>>>(N, 3 * E);

    gru_fused<<<dim3(mb, 4, 3), 256, FSMEM>>>(
        N,
        (const float*)d_in[10], (const float*)d_in[11],
        (const float*)d_in[17], (const float*)d_in[18],
        (const float*)d_in[24], (const float*)d_in[25]);

    final_sem_k<<<(N * 32 + 255) / 256, 256>>>(out, (const float*)d_in[27], N);
}